// round 2
// baseline (speedup 1.0000x reference)
#include <cuda_runtime.h>

// SegmenterTensorFlow: windowed framing + overlap-add reconstruction.
// B=8, N=4194304, seg=1024, hop=512 -> NSEG=8191, out_len=N.
//
// d_out layout: X [B, NSEG, SEG] followed by x_rec [B, N].
//
// hop = seg/2 => each sample n belongs to exactly two segments:
//   s0 = n>>9, j = m = n&511       (invalid when s0 == NSEG)
//   s0-1,     j = m + 512          (invalid when s0 == 0)
// x_rec[b,n] = x[b,n] * (v0*aw[m]*sw[m] + v1*aw[m+512]*sw[m+512]).
//
// R2: 2 float4 per thread (higher MLP), streaming cache hints (.cs) on the
// bulk streams so the 400MB of writes don't thrash L2.

#define BB   8
#define NN   4194304
#define SEG  1024
#define HOP  512
#define NSEG 8191

__device__ __forceinline__ float4 ldcs4(const float* p) {
    return __ldcs(reinterpret_cast<const float4*>(p));
}
__device__ __forceinline__ void stcs4(float* p, float4 v) {
    __stcs(reinterpret_cast<float4*>(p), v);
}
__device__ __forceinline__ float4 mul4(float4 a, float4 b) {
    float4 r; r.x = a.x*b.x; r.y = a.y*b.y; r.z = a.z*b.z; r.w = a.w*b.w;
    return r;
}

__global__ __launch_bounds__(256)
void seg_olap_kernel(const float* __restrict__ x,
                     const float* __restrict__ aw,
                     const float* __restrict__ sw,
                     float* __restrict__ Xout,
                     float* __restrict__ rec)
{
    long long t = (long long)blockIdx.x * blockDim.x + threadIdx.x;
    long long i = t << 3;                       // 8 floats (2 x float4) per thread
    if (i >= (long long)BB * NN) return;

    int b  = (int)(i >> 22);                    // N = 2^22
    int n  = (int)(i & (NN - 1));
    int m  = n & (HOP - 1);                     // 8-aligned; both vec4s share s0
    int s0 = n >> 9;

    const bool v0 = (s0 < NSEG);
    const bool v1 = (s0 >= 1);

    // Issue both x loads up front (independent -> MLP=2)
    float4 xa = ldcs4(x + i);
    float4 xb = ldcs4(x + i + 4);

    // Windows: small, L1/L2-resident
    const float4* awv = reinterpret_cast<const float4*>(aw);
    const float4* swv = reinterpret_cast<const float4*>(sw);
    int mq = m >> 2;
    float4 awl0 = __ldg(awv + mq),            awl1 = __ldg(awv + mq + 1);
    float4 awh0 = __ldg(awv + mq + HOP/4),    awh1 = __ldg(awv + mq + HOP/4 + 1);
    float4 swl0 = __ldg(swv + mq),            swl1 = __ldg(swv + mq + 1);
    float4 swh0 = __ldg(swv + mq + HOP/4),    swh1 = __ldg(swv + mq + HOP/4 + 1);

    // X writes: segment s0 at offset m (lo), segment s0-1 at offset m+512 (hi)
    if (v0) {
        size_t off = ((size_t)b * NSEG + s0) * SEG + m;
        stcs4(Xout + off,     mul4(xa, awl0));
        stcs4(Xout + off + 4, mul4(xb, awl1));
    }
    if (v1) {
        size_t off = ((size_t)b * NSEG + (s0 - 1)) * SEG + (m + HOP);
        stcs4(Xout + off,     mul4(xa, awh0));
        stcs4(Xout + off + 4, mul4(xb, awh1));
    }

    // overlap-add collapses to a pointwise weight
    float w0 = v0 ? 1.0f : 0.0f;
    float w1 = v1 ? 1.0f : 0.0f;
    float4 r0, r1;
    r0.x = xa.x * (w0*awl0.x*swl0.x + w1*awh0.x*swh0.x);
    r0.y = xa.y * (w0*awl0.y*swl0.y + w1*awh0.y*swh0.y);
    r0.z = xa.z * (w0*awl0.z*swl0.z + w1*awh0.z*swh0.z);
    r0.w = xa.w * (w0*awl0.w*swl0.w + w1*awh0.w*swh0.w);
    r1.x = xb.x * (w0*awl1.x*swl1.x + w1*awh1.x*swh1.x);
    r1.y = xb.y * (w0*awl1.y*swl1.y + w1*awh1.y*swh1.y);
    r1.z = xb.z * (w0*awl1.z*swl1.z + w1*awh1.z*swh1.z);
    r1.w = xb.w * (w0*awl1.w*swl1.w + w1*awh1.w*swh1.w);
    stcs4(rec + i,     r0);
    stcs4(rec + i + 4, r1);
}

extern "C" void kernel_launch(void* const* d_in, const int* in_sizes, int n_in,
                              void* d_out, int out_size)
{
    const float* x  = (const float*)d_in[0];
    const float* aw = (const float*)d_in[1];
    const float* sw = (const float*)d_in[2];

    float* Xout = (float*)d_out;
    float* rec  = Xout + (size_t)BB * NSEG * SEG;

    const long long total = (long long)BB * NN;           // 33,554,432 floats
    const long long per_thread = 8;
    const int threads = 256;
    const long long nthreads = total / per_thread;          // 4,194,304
    const int blocks = (int)((nthreads + threads - 1) / threads);

    seg_olap_kernel<<<blocks, threads>>>(x, aw, sw, Xout, rec);
}

// round 3
// speedup vs baseline: 1.3980x; 1.3980x over previous
#include <cuda_runtime.h>

// SegmenterTensorFlow: windowed framing + overlap-add reconstruction.
// B=8, N=4194304, seg=1024, hop=512 -> NSEG=8191, out_len=N.
//
// d_out layout: X [B, NSEG, SEG] followed by x_rec [B, N].
//
// hop = seg/2 => each sample n belongs to exactly two segments:
//   s0 = n>>9, j = m = n&511       (invalid when s0 == NSEG)
//   s0-1,     j = m + 512          (invalid when s0 == 0)
// x_rec[b,n] = x[b,n] * (v0*aw[m]*sw[m] + v1*aw[m+512]*sw[m+512]).
//
// R3: exactly R1's structure (1 float4/thread, 37 regs, occ ~57%) plus
// evict-first (.cs) cache hints on the three bulk streams only.
// R2's 2x unroll is reverted: it cost 58 regs -> 41% occ -> 112us.

#define BB   8
#define NN   4194304
#define SEG  1024
#define HOP  512
#define NSEG 8191

__global__ __launch_bounds__(256)
void seg_olap_kernel(const float* __restrict__ x,
                     const float* __restrict__ aw,
                     const float* __restrict__ sw,
                     float* __restrict__ Xout,
                     float* __restrict__ rec)
{
    long long t = (long long)blockIdx.x * blockDim.x + threadIdx.x;
    long long i = t << 2;                       // element index into [B*N]
    if (i >= (long long)BB * NN) return;

    int b = (int)(i >> 22);                     // N = 2^22
    int n = (int)(i & (NN - 1));
    int m = n & (HOP - 1);                      // uniform mod-512 phase (vec-aligned)
    int s0 = n >> 9;

    const bool v0 = (s0 < NSEG);                // segment s0, offset m
    const bool v1 = (s0 >= 1);                  // segment s0-1, offset m+512

    // streaming read of x (read-once)
    float4 xv = __ldcs(reinterpret_cast<const float4*>(x + i));

    // windows: tiny, keep normal caching
    float4 awl = *reinterpret_cast<const float4*>(aw + m);
    float4 awh = *reinterpret_cast<const float4*>(aw + m + HOP);
    float4 swl = *reinterpret_cast<const float4*>(sw + m);
    float4 swh = *reinterpret_cast<const float4*>(sw + m + HOP);

    // X writes (coalesced: consecutive n -> consecutive j within a segment row)
    if (v0) {
        float4 lo;
        lo.x = xv.x * awl.x; lo.y = xv.y * awl.y;
        lo.z = xv.z * awl.z; lo.w = xv.w * awl.w;
        size_t off = ((size_t)b * NSEG + s0) * SEG + m;
        __stcs(reinterpret_cast<float4*>(Xout + off), lo);
    }
    if (v1) {
        float4 hi;
        hi.x = xv.x * awh.x; hi.y = xv.y * awh.y;
        hi.z = xv.z * awh.z; hi.w = xv.w * awh.w;
        size_t off = ((size_t)b * NSEG + (s0 - 1)) * SEG + (m + HOP);
        __stcs(reinterpret_cast<float4*>(Xout + off), hi);
    }

    // overlap-add collapses to pointwise weight
    float w0 = v0 ? 1.0f : 0.0f;
    float w1 = v1 ? 1.0f : 0.0f;
    float4 r;
    r.x = xv.x * (w0 * awl.x * swl.x + w1 * awh.x * swh.x);
    r.y = xv.y * (w0 * awl.y * swl.y + w1 * awh.y * swh.y);
    r.z = xv.z * (w0 * awl.z * swl.z + w1 * awh.z * swh.z);
    r.w = xv.w * (w0 * awl.w * swl.w + w1 * awh.w * swh.w);
    __stcs(reinterpret_cast<float4*>(rec + i), r);
}

extern "C" void kernel_launch(void* const* d_in, const int* in_sizes, int n_in,
                              void* d_out, int out_size)
{
    const float* x  = (const float*)d_in[0];
    const float* aw = (const float*)d_in[1];
    const float* sw = (const float*)d_in[2];

    float* Xout = (float*)d_out;
    float* rec  = Xout + (size_t)BB * NSEG * SEG;

    const long long total_vec4 = ((long long)BB * NN) / 4;   // 8,388,608
    const int threads = 256;
    const int blocks = (int)((total_vec4 + threads - 1) / threads);

    seg_olap_kernel<<<blocks, threads>>>(x, aw, sw, Xout, rec);
}